// round 5
// baseline (speedup 1.0000x reference)
#include <cuda_runtime.h>

#define D_IN   64
#define D_OUT  64
#define D_HID  128
#define MAX_NODES 100000
#define NPB    128                 // nodes per block in main kernel
#define NT     256                 // threads per block in main kernel
#define PREP_BLOCKS 65             // W12 rows + bW
#define EPT    8                   // edges per thread in hist

// Scratch. g_deg relies on the consume-reset invariant: zero at module load,
// gnn_main_kernel resets each entry after reading it.
__device__ int   g_deg[MAX_NODES];
__device__ float g_W12[D_IN * D_OUT];
__device__ float g_bW[D_OUT];

// ---------------------------------------------------------------------------
// Packed f32x2 helpers (sm_103a FFMA2 path)
__device__ __forceinline__ unsigned long long fma2(unsigned long long a,
                                                   unsigned long long b,
                                                   unsigned long long c) {
    unsigned long long d;
    asm("fma.rn.f32x2 %0, %1, %2, %3;" : "=l"(d) : "l"(a), "l"(b), "l"(c));
    return d;
}
__device__ __forceinline__ unsigned long long bcast2(float x) {
    unsigned int xi = __float_as_uint(x);
    unsigned long long d;
    asm("mov.b64 %0, {%1, %1};" : "=l"(d) : "r"(xi));
    return d;
}
__device__ __forceinline__ void unpack2(unsigned long long v, float& lo, float& hi) {
    unsigned int a, b;
    asm("mov.b64 {%0, %1}, %2;" : "=r"(a), "=r"(b) : "l"(v));
    lo = __uint_as_float(a); hi = __uint_as_float(b);
}

// ---------------------------------------------------------------------------
// K1: blocks [0, PREP_BLOCKS) precompute W12 = W1@W2 and bW = b1@W2.
//     Remaining blocks build the degree histogram (self-detecting dtype).
__global__ __launch_bounds__(256) void prep_hist_kernel(
    const int* __restrict__ ei32,
    const float* __restrict__ W1,
    const float* __restrict__ b1,
    const float* __restrict__ W2,
    int E)
{
    const int tid = threadIdx.x;

    if (blockIdx.x < PREP_BLOCKS) {
        const int r  = blockIdx.x;
        const int j  = tid & 63;
        const int kc = tid >> 6;
        const float* src = (r < D_IN) ? (W1 + (size_t)r * D_HID) : b1;

        float a = 0.f;
        #pragma unroll 8
        for (int k = kc * 32; k < kc * 32 + 32; ++k)
            a = fmaf(src[k], W2[(size_t)k * D_OUT + j], a);

        __shared__ float red[4][64];
        red[kc][j] = a;
        __syncthreads();
        if (kc == 0) {
            float v = red[0][j] + red[1][j] + red[2][j] + red[3][j];
            if (r < D_IN) g_W12[r * D_OUT + j] = v;
            else          g_bW[j] = v;
        }
        return;
    }

    // ---- histogram over edge_index[1] (dst row) ----
    __shared__ int s_is64;
    if (tid == 0) {
        int is64 = 1;
        #pragma unroll
        for (int i = 1; i < 64; i += 2)
            if (ei32[i] != 0) is64 = 0;
        s_is64 = is64;
    }
    __syncthreads();

    const int hb = blockIdx.x - PREP_BLOCKS;
    const long long i0 = ((long long)hb * 256 + tid) * EPT;
    if (i0 >= E) return;

    if (s_is64) {
        const unsigned long long* p = (const unsigned long long*)ei32 + E;
        if (i0 + EPT <= E) {
            const ulonglong2* q = (const ulonglong2*)(p + i0);
            #pragma unroll
            for (int c = 0; c < EPT / 2; ++c) {
                ulonglong2 v = q[c];
                atomicAdd(&g_deg[(int)v.x], 1);
                atomicAdd(&g_deg[(int)v.y], 1);
            }
        } else {
            for (long long j = i0; j < E; ++j) atomicAdd(&g_deg[(int)p[j]], 1);
        }
    } else {
        const int* p = (const int*)ei32 + E;
        if (i0 + EPT <= E) {
            const int4* q = (const int4*)(p + i0);
            #pragma unroll
            for (int c = 0; c < EPT / 4; ++c) {
                int4 v = q[c];
                atomicAdd(&g_deg[v.x], 1); atomicAdd(&g_deg[v.y], 1);
                atomicAdd(&g_deg[v.z], 1); atomicAdd(&g_deg[v.w], 1);
            }
        } else {
            for (long long j = i0; j < E; ++j) atomicAdd(&g_deg[p[j]], 1);
        }
    }
}

// ---------------------------------------------------------------------------
// K2: out[n] = (1+deg[n]) * (x[n] @ W12 + bW) + b2, then deg[n] := 0.
// 256 threads / 128 nodes per block, 3 blocks/SM (24 warps).
// Thread (g = tid>>2, q = tid&3) computes cols {16v+4q..+3 : v=0..3} for the
// 2 nodes {2g, 2g+1}. x is read by LDG.128 (4 lanes share each address ->
// broadcast); weights come from a 16KB smem tile via conflict-free LDS.128.
__global__ __launch_bounds__(NT, 3) void gnn_main_kernel(
    const float* __restrict__ x,
    const float* __restrict__ b2,
    float* __restrict__ out,
    int n)
{
    __shared__ float w12[D_IN * D_OUT];
    __shared__ float bw_s[D_OUT];
    __shared__ float b2_s[D_OUT];

    const int tid  = threadIdx.x;
    const int base = blockIdx.x * NPB;
    const int q    = tid & 3;
    const int g    = tid >> 2;
    const int n0   = base + g * 2;               // first of this thread's 2 nodes

    // Early degree prefetch (hides under the FMA loop).
    int deg0 = (n0     < n) ? g_deg[n0]     : 0;
    int deg1 = (n0 + 1 < n) ? g_deg[n0 + 1] : 0;

    // Stage W12 (1024 float4 / 256 thr = 4 each) + biases.
    #pragma unroll
    for (int i = tid; i < D_IN * D_OUT / 4; i += NT)
        ((float4*)w12)[i] = ((const float4*)g_W12)[i];
    if (tid < D_OUT) { bw_s[tid] = g_bW[tid]; b2_s[tid] = b2[tid]; }
    __syncthreads();

    // x row pointers (clamped for tail so loads stay in-bounds).
    const int r0 = (n0     < n) ? n0     : 0;
    const int r1 = (n0 + 1 < n) ? n0 + 1 : 0;
    const float4* xp0 = (const float4*)(x + (size_t)r0 * D_IN);
    const float4* xp1 = (const float4*)(x + (size_t)r1 * D_IN);

    unsigned long long acc[2][8];
    #pragma unroll
    for (int i = 0; i < 2; ++i)
        #pragma unroll
        for (int j = 0; j < 8; ++j) acc[i][j] = 0ull;

    const float* wq = w12 + 4 * q;

    #pragma unroll 4
    for (int kc = 0; kc < D_IN / 4; ++kc) {
        const float4 xa = xp0[kc];               // 4 k-values, node 0
        const float4 xb = xp1[kc];               // 4 k-values, node 1
        const float xav[4] = {xa.x, xa.y, xa.z, xa.w};
        const float xbv[4] = {xb.x, xb.y, xb.z, xb.w};

        #pragma unroll
        for (int kk = 0; kk < 4; ++kk) {
            const float* wr = wq + (kc * 4 + kk) * D_OUT;
            ulonglong2 w0 = *(const ulonglong2*)(wr);
            ulonglong2 w1 = *(const ulonglong2*)(wr + 16);
            ulonglong2 w2 = *(const ulonglong2*)(wr + 32);
            ulonglong2 w3 = *(const ulonglong2*)(wr + 48);
            unsigned long long w[8] = {w0.x, w0.y, w1.x, w1.y,
                                       w2.x, w2.y, w3.x, w3.y};
            const unsigned long long pa = bcast2(xav[kk]);
            const unsigned long long pb = bcast2(xbv[kk]);
            #pragma unroll
            for (int j = 0; j < 8; ++j) {
                acc[0][j] = fma2(pa, w[j], acc[0][j]);
                acc[1][j] = fma2(pb, w[j], acc[1][j]);
            }
        }
    }

    // Epilogue: scale by (1+deg), add biases, store; reset deg for next call.
    #pragma unroll
    for (int i = 0; i < 2; ++i) {
        const int node = n0 + i;
        if (node >= n) break;
        const float s = 1.0f + (float)(i == 0 ? deg0 : deg1);
        if (q == 0) g_deg[node] = 0;             // consume-reset
        #pragma unroll
        for (int v = 0; v < 4; ++v) {
            const int c = v * 16 + 4 * q;
            float lo0, hi0, lo1, hi1;
            unpack2(acc[i][2 * v],     lo0, hi0);
            unpack2(acc[i][2 * v + 1], lo1, hi1);
            float4 r;
            r.x = fmaf(s, lo0 + bw_s[c + 0], b2_s[c + 0]);
            r.y = fmaf(s, hi0 + bw_s[c + 1], b2_s[c + 1]);
            r.z = fmaf(s, lo1 + bw_s[c + 2], b2_s[c + 2]);
            r.w = fmaf(s, hi1 + bw_s[c + 3], b2_s[c + 3]);
            *(float4*)(out + (size_t)node * D_OUT + c) = r;
        }
    }
}

// ---------------------------------------------------------------------------
extern "C" void kernel_launch(void* const* d_in, const int* in_sizes, int n_in,
                              void* d_out, int out_size) {
    const float* x  = (const float*)d_in[0];
    const void*  ei = d_in[1];
    const float* W1 = (const float*)d_in[2];
    const float* b1 = (const float*)d_in[3];
    const float* W2 = (const float*)d_in[4];
    const float* b2 = (const float*)d_in[5];
    float* out = (float*)d_out;

    const int n = in_sizes[0] / D_IN;   // 100000
    const int E = in_sizes[1] / 2;      // 1000000

    const int hist_blocks = (E + 256 * EPT - 1) / (256 * EPT);
    prep_hist_kernel<<<PREP_BLOCKS + hist_blocks, 256>>>(
        (const int*)ei, W1, b1, W2, E);

    gnn_main_kernel<<<(n + NPB - 1) / NPB, NT>>>(x, b2, out, n);
}

// round 7
// speedup vs baseline: 1.6334x; 1.6334x over previous
#include <cuda_runtime.h>
#include <cuda_bf16.h>
#include <cstdint>

#define D_IN   64
#define D_OUT  64
#define D_HID  128
#define MAX_NODES 100000
#define NPB    128                 // nodes per block (M tile)
#define NT     256                 // threads per block (8 warps x 16 rows)
#define PREP_BLOCKS 65
#define EPT    8

// Row strides (padded, conflict-free fragment LDS)
#define WS     72                  // bf16 elems per W row (144 B)
#define XS     72                  // bf16 elems per x row (144 B)
#define DS     68                  // f32 elems per D row (272 B, 16B-aligned)

// Scratch. g_deg: consume-reset invariant (zero at load, reset after read).
__device__ int   g_deg[MAX_NODES];
__device__ float g_bW[D_OUT];
// W12^T row-major [c][k], bf16 hi/lo (k contiguous).
__device__ __align__(16) unsigned short g_WT_h[D_OUT * D_IN];
__device__ __align__(16) unsigned short g_WT_l[D_OUT * D_IN];

// ---------------------------------------------------------------------------
__device__ __forceinline__ void mma_bf16(float& d0, float& d1, float& d2, float& d3,
                                         uint32_t a0, uint32_t a1, uint32_t a2, uint32_t a3,
                                         uint32_t b0, uint32_t b1) {
    asm volatile(
        "mma.sync.aligned.m16n8k16.row.col.f32.bf16.bf16.f32 "
        "{%0,%1,%2,%3}, {%4,%5,%6,%7}, {%8,%9}, {%0,%1,%2,%3};"
        : "+f"(d0), "+f"(d1), "+f"(d2), "+f"(d3)
        : "r"(a0), "r"(a1), "r"(a2), "r"(a3), "r"(b0), "r"(b1));
}

// ---------------------------------------------------------------------------
// K1: blocks [0,65) -> W12^T hi/lo bf16 + bW. Rest: degree histogram.
__global__ __launch_bounds__(256) void prep_hist_kernel(
    const int* __restrict__ ei32,
    const float* __restrict__ W1,
    const float* __restrict__ b1,
    const float* __restrict__ W2,
    int E)
{
    const int tid = threadIdx.x;

    if (blockIdx.x < PREP_BLOCKS) {
        const int r  = blockIdx.x;       // k index (or 64 => bW)
        const int j  = tid & 63;         // output column c
        const int kc = tid >> 6;
        const float* src = (r < D_IN) ? (W1 + (size_t)r * D_HID) : b1;

        float a = 0.f;
        #pragma unroll 8
        for (int k = kc * 32; k < kc * 32 + 32; ++k)
            a = fmaf(src[k], W2[(size_t)k * D_OUT + j], a);

        __shared__ float red[4][64];
        red[kc][j] = a;
        __syncthreads();
        if (kc == 0) {
            float v = red[0][j] + red[1][j] + red[2][j] + red[3][j];
            if (r < D_IN) {
                __nv_bfloat16 h = __float2bfloat16_rn(v);
                __nv_bfloat16 l = __float2bfloat16_rn(v - __bfloat162float(h));
                g_WT_h[j * D_IN + r] = *reinterpret_cast<unsigned short*>(&h);
                g_WT_l[j * D_IN + r] = *reinterpret_cast<unsigned short*>(&l);
            } else {
                g_bW[j] = v;
            }
        }
        return;
    }

    // ---- histogram over edge_index[1] (dst row), dtype self-detecting ----
    __shared__ int s_is64;
    if (tid == 0) {
        int is64 = 1;
        #pragma unroll
        for (int i = 1; i < 64; i += 2)
            if (ei32[i] != 0) is64 = 0;
        s_is64 = is64;
    }
    __syncthreads();

    const int hb = blockIdx.x - PREP_BLOCKS;
    const long long i0 = ((long long)hb * 256 + tid) * EPT;
    if (i0 >= E) return;

    if (s_is64) {
        const unsigned long long* p = (const unsigned long long*)ei32 + E;
        if (i0 + EPT <= E) {
            const ulonglong2* q = (const ulonglong2*)(p + i0);
            #pragma unroll
            for (int c = 0; c < EPT / 2; ++c) {
                ulonglong2 v = q[c];
                atomicAdd(&g_deg[(int)v.x], 1);
                atomicAdd(&g_deg[(int)v.y], 1);
            }
        } else {
            for (long long j = i0; j < E; ++j) atomicAdd(&g_deg[(int)p[j]], 1);
        }
    } else {
        const int* p = (const int*)ei32 + E;
        if (i0 + EPT <= E) {
            const int4* q = (const int4*)(p + i0);
            #pragma unroll
            for (int c = 0; c < EPT / 4; ++c) {
                int4 v = q[c];
                atomicAdd(&g_deg[v.x], 1); atomicAdd(&g_deg[v.y], 1);
                atomicAdd(&g_deg[v.z], 1); atomicAdd(&g_deg[v.w], 1);
            }
        } else {
            for (long long j = i0; j < E; ++j) atomicAdd(&g_deg[p[j]], 1);
        }
    }
}

// ---------------------------------------------------------------------------
// SMEM byte offsets (dynamic)
#define SM_SC  0                              // 128 f32 scales (1+deg)
#define SM_BW  512                            // 64 f32
#define SM_B2  768                            // 64 f32
#define SM_WH  1024                           // 64 x 144B
#define SM_WL  (SM_WH + 64 * 144)             // 64 x 144B
#define SM_XH  (SM_WL + 64 * 144)             // 128 x 144B
#define SM_XL  (SM_XH + 128 * 144)            // 128 x 144B
#define SM_D   SM_XH                          // reused: 128 x 272B = 34816
#define SM_TOTAL (SM_XL + 128 * 144)          // 56320 B

// K2 (HMMA): per block of 128 nodes, D = xh@Wh + xh@Wl + xl@Wh (fp32 acc),
//            out[n] = (1+deg)*(D[n] + bW) + b2
__global__ __launch_bounds__(NT) void gnn_mma_kernel(
    const float* __restrict__ x,
    const float* __restrict__ b2,
    float* __restrict__ out,
    int n)
{
    extern __shared__ char smem[];
    const int tid = threadIdx.x;
    const int wid = tid >> 5;
    const int lid = tid & 31;
    const int g   = lid >> 2;                  // 0..7
    const int t   = lid & 3;                   // 0..3
    const int base = blockIdx.x * NPB;

    // Degree read + consume-reset + scale into smem
    if (tid < NPB) {
        const int node = base + tid;
        int d = 0;
        if (node < n) { d = g_deg[node]; g_deg[node] = 0; }
        ((float*)(smem + SM_SC))[tid] = 1.0f + (float)d;
    }
    if (tid < D_OUT) {
        ((float*)(smem + SM_BW))[tid] = g_bW[tid];
        ((float*)(smem + SM_B2))[tid] = b2[tid];
    }

    // Stage W^T hi/lo: 64 rows x 64 bf16 (=16 uint2/row) -> padded rows
    #pragma unroll
    for (int it = 0; it < 4; ++it) {
        const int u = it * NT + tid;           // 0..1023
        const int c = u >> 4, q = u & 15;
        *(uint2*)(smem + SM_WH + c * 144 + q * 8) =
            *(const uint2*)((const char*)g_WT_h + c * 128 + q * 8);
        *(uint2*)(smem + SM_WL + c * 144 + q * 8) =
            *(const uint2*)((const char*)g_WT_l + c * 128 + q * 8);
    }

    // Stage x: f32 -> bf16 hi/lo, padded rows
    #pragma unroll
    for (int it = 0; it < 8; ++it) {
        const int u = it * NT + tid;           // 0..2047
        const int row = u >> 4, q4 = u & 15;
        const int gr = (base + row < n) ? (base + row) : (n > 0 ? n - 1 : 0);
        const float4 v = ((const float4*)(x + (size_t)gr * D_IN))[q4];

        __nv_bfloat16 h0 = __float2bfloat16_rn(v.x);
        __nv_bfloat16 h1 = __float2bfloat16_rn(v.y);
        __nv_bfloat16 h2 = __float2bfloat16_rn(v.z);
        __nv_bfloat16 h3 = __float2bfloat16_rn(v.w);
        __nv_bfloat16 l0 = __float2bfloat16_rn(v.x - __bfloat162float(h0));
        __nv_bfloat16 l1 = __float2bfloat16_rn(v.y - __bfloat162float(h1));
        __nv_bfloat16 l2 = __float2bfloat16_rn(v.z - __bfloat162float(h2));
        __nv_bfloat16 l3 = __float2bfloat16_rn(v.w - __bfloat162float(h3));

        uint2 hv, lv;
        __nv_bfloat162 p;
        p = __halves2bfloat162(h0, h1); hv.x = *reinterpret_cast<uint32_t*>(&p);
        p = __halves2bfloat162(h2, h3); hv.y = *reinterpret_cast<uint32_t*>(&p);
        p = __halves2bfloat162(l0, l1); lv.x = *reinterpret_cast<uint32_t*>(&p);
        p = __halves2bfloat162(l2, l3); lv.y = *reinterpret_cast<uint32_t*>(&p);

        *(uint2*)(smem + SM_XH + row * 144 + q4 * 8) = hv;
        *(uint2*)(smem + SM_XL + row * 144 + q4 * 8) = lv;
    }
    __syncthreads();

    // ---- HMMA mainloop: warp owns rows [16*wid, 16*wid+16) ----
    float acc[32];                             // 8 n-tiles x {d0,d1,d2,d3}
    #pragma unroll
    for (int i = 0; i < 32; ++i) acc[i] = 0.f;

    const int rowA  = wid * 16 + g;            // A row for a0/a2
    const uint32_t aoff = (uint32_t)(rowA * 144 + 4 * t);
    const uint32_t boff = (uint32_t)(g * 144 + 4 * t);

    #pragma unroll
    for (int ks = 0; ks < 4; ++ks) {
        const uint32_t ak = aoff + ks * 32;
        const uint32_t ah0 = *(const uint32_t*)(smem + SM_XH + ak);
        const uint32_t ah1 = *(const uint32_t*)(smem + SM_XH + ak + 8 * 144);
        const uint32_t ah2 = *(const uint32_t*)(smem + SM_XH + ak + 16);
        const uint32_t ah3 = *(const uint32_t*)(smem + SM_XH + ak + 8 * 144 + 16);
        const uint32_t al0 = *(const uint32_t*)(smem + SM_XL + ak);
        const uint32_t al1 = *(const uint32_t*)(smem + SM_XL + ak + 8 * 144);
        const uint32_t al2 = *(const uint32_t*)(smem + SM_XL + ak + 16);
        const uint32_t al3 = *(const uint32_t*)(smem + SM_XL + ak + 8 * 144 + 16);

        #pragma unroll
        for (int nt = 0; nt < 8; ++nt) {
            const uint32_t bk = boff + nt * 8 * 144 + ks * 32;
            const uint32_t bh0 = *(const uint32_t*)(smem + SM_WH + bk);
            const uint32_t bh1 = *(const uint32_t*)(smem + SM_WH + bk + 16);
            const uint32_t bl0 = *(const uint32_t*)(smem + SM_WL + bk);
            const uint32_t bl1 = *(const uint32_t*)(smem + SM_WL + bk + 16);
            float* a = acc + nt * 4;
            mma_bf16(a[0], a[1], a[2], a[3], ah0, ah1, ah2, ah3, bh0, bh1);
            mma_bf16(a[0], a[1], a[2], a[3], ah0, ah1, ah2, ah3, bl0, bl1);
            mma_bf16(a[0], a[1], a[2], a[3], al0, al1, al2, al3, bh0, bh1);
        }
    }
    __syncthreads();                           // all x reads done; reuse as D

    // D fragments -> smem (float2 per (row, n-tile))
    {
        float* Dm = (float*)(smem + SM_D);
        const int r0 = wid * 16 + g;
        #pragma unroll
        for (int nt = 0; nt < 8; ++nt) {
            const int c = nt * 8 + 2 * t;
            *(float2*)(Dm + r0 * DS + c)       = make_float2(acc[nt*4+0], acc[nt*4+1]);
            *(float2*)(Dm + (r0 + 8) * DS + c) = make_float2(acc[nt*4+2], acc[nt*4+3]);
        }
    }
    __syncthreads();

    // Scaled, biased, coalesced output
    {
        const float* Dm = (const float*)(smem + SM_D);
        const float* sc = (const float*)(smem + SM_SC);
        const float* bw = (const float*)(smem + SM_BW);
        const float* bb = (const float*)(smem + SM_B2);
        #pragma unroll
        for (int it = 0; it < 8; ++it) {
            const int u = it * NT + tid;       // 0..2047
            const int row = u >> 4, c4 = u & 15;
            const int node = base + row;
            if (node < n) {
                const float s = sc[row];
                const float4 v = *(const float4*)(Dm + row * DS + c4 * 4);
                const int c = c4 * 4;
                float4 r;
                r.x = fmaf(s, v.x + bw[c + 0], bb[c + 0]);
                r.y = fmaf(s, v.y + bw[c + 1], bb[c + 1]);
                r.z = fmaf(s, v.z + bw[c + 2], bb[c + 2]);
                r.w = fmaf(s, v.w + bw[c + 3], bb[c + 3]);
                *(float4*)(out + (size_t)node * D_OUT + c) = r;
            }
        }
    }
}

// ---------------------------------------------------------------------------
extern "C" void kernel_launch(void* const* d_in, const int* in_sizes, int n_in,
                              void* d_out, int out_size) {
    const float* x  = (const float*)d_in[0];
    const void*  ei = d_in[1];
    const float* W1 = (const float*)d_in[2];
    const float* b1 = (const float*)d_in[3];
    const float* W2 = (const float*)d_in[4];
    const float* b2 = (const float*)d_in[5];
    float* out = (float*)d_out;

    const int n = in_sizes[0] / D_IN;   // 100000
    const int E = in_sizes[1] / 2;      // 1000000

    const int hist_blocks = (E + 256 * EPT - 1) / (256 * EPT);
    prep_hist_kernel<<<PREP_BLOCKS + hist_blocks, 256>>>(
        (const int*)ei, W1, b1, W2, E);

    cudaFuncSetAttribute(gnn_mma_kernel,
                         cudaFuncAttributeMaxDynamicSharedMemorySize, SM_TOTAL);
    gnn_mma_kernel<<<(n + NPB - 1) / NPB, NT, SM_TOTAL>>>(x, b2, out, n);
}

// round 8
// speedup vs baseline: 1.7547x; 1.0743x over previous
#include <cuda_runtime.h>
#include <cuda_bf16.h>
#include <cstdint>

#define D_IN   64
#define D_OUT  64
#define D_HID  128
#define MAX_NODES 100000
#define NPB    128                 // nodes per block (M tile)
#define NT     256                 // threads per block (8 warps x 16 rows)
#define PREP_BLOCKS 65
#define EPT    8

// Scratch. g_deg: consume-reset invariant (zero at load, reset after read).
__device__ int   g_deg[MAX_NODES];
__device__ float g_bW[D_OUT];
// W12^T row-major [c][k], bf16 hi/lo (k contiguous).
__device__ __align__(16) unsigned short g_WT_h[D_OUT * D_IN];
__device__ __align__(16) unsigned short g_WT_l[D_OUT * D_IN];

// ---------------------------------------------------------------------------
__device__ __forceinline__ void mma_bf16(float& d0, float& d1, float& d2, float& d3,
                                         uint32_t a0, uint32_t a1, uint32_t a2, uint32_t a3,
                                         uint32_t b0, uint32_t b1) {
    asm volatile(
        "mma.sync.aligned.m16n8k16.row.col.f32.bf16.bf16.f32 "
        "{%0,%1,%2,%3}, {%4,%5,%6,%7}, {%8,%9}, {%0,%1,%2,%3};"
        : "+f"(d0), "+f"(d1), "+f"(d2), "+f"(d3)
        : "r"(a0), "r"(a1), "r"(a2), "r"(a3), "r"(b0), "r"(b1));
}

// ---------------------------------------------------------------------------
// K1: blocks [0,65) -> W12^T hi/lo bf16 + bW. Rest: degree histogram.
__global__ __launch_bounds__(256) void prep_hist_kernel(
    const int* __restrict__ ei32,
    const float* __restrict__ W1,
    const float* __restrict__ b1,
    const float* __restrict__ W2,
    int E)
{
    const int tid = threadIdx.x;

    if (blockIdx.x < PREP_BLOCKS) {
        const int r  = blockIdx.x;       // k index (or 64 => bW)
        const int j  = tid & 63;         // output column c
        const int kc = tid >> 6;
        const float* src = (r < D_IN) ? (W1 + (size_t)r * D_HID) : b1;

        float a = 0.f;
        #pragma unroll 8
        for (int k = kc * 32; k < kc * 32 + 32; ++k)
            a = fmaf(src[k], W2[(size_t)k * D_OUT + j], a);

        __shared__ float red[4][64];
        red[kc][j] = a;
        __syncthreads();
        if (kc == 0) {
            float v = red[0][j] + red[1][j] + red[2][j] + red[3][j];
            if (r < D_IN) {
                __nv_bfloat16 h = __float2bfloat16_rn(v);
                __nv_bfloat16 l = __float2bfloat16_rn(v - __bfloat162float(h));
                g_WT_h[j * D_IN + r] = *reinterpret_cast<unsigned short*>(&h);
                g_WT_l[j * D_IN + r] = *reinterpret_cast<unsigned short*>(&l);
            } else {
                g_bW[j] = v;
            }
        }
        return;
    }

    // ---- histogram over edge_index[1] (dst row), dtype self-detecting ----
    __shared__ int s_is64;
    if (tid == 0) {
        int is64 = 1;
        #pragma unroll
        for (int i = 1; i < 64; i += 2)
            if (ei32[i] != 0) is64 = 0;
        s_is64 = is64;
    }
    __syncthreads();

    const int hb = blockIdx.x - PREP_BLOCKS;
    const long long i0 = ((long long)hb * 256 + tid) * EPT;
    if (i0 >= E) return;

    if (s_is64) {
        const unsigned long long* p = (const unsigned long long*)ei32 + E;
        if (i0 + EPT <= E) {
            const ulonglong2* q = (const ulonglong2*)(p + i0);
            #pragma unroll
            for (int c = 0; c < EPT / 2; ++c) {
                ulonglong2 v = q[c];
                atomicAdd(&g_deg[(int)v.x], 1);
                atomicAdd(&g_deg[(int)v.y], 1);
            }
        } else {
            for (long long j = i0; j < E; ++j) atomicAdd(&g_deg[(int)p[j]], 1);
        }
    } else {
        const int* p = (const int*)ei32 + E;
        if (i0 + EPT <= E) {
            const int4* q = (const int4*)(p + i0);
            #pragma unroll
            for (int c = 0; c < EPT / 4; ++c) {
                int4 v = q[c];
                atomicAdd(&g_deg[v.x], 1); atomicAdd(&g_deg[v.y], 1);
                atomicAdd(&g_deg[v.z], 1); atomicAdd(&g_deg[v.w], 1);
            }
        } else {
            for (long long j = i0; j < E; ++j) atomicAdd(&g_deg[p[j]], 1);
        }
    }
}

// ---------------------------------------------------------------------------
// SMEM byte offsets (dynamic)
#define SM_SC  0                              // 128 f32 scales (1+deg)
#define SM_BW  512                            // 64 f32
#define SM_B2  768                            // 64 f32
#define SM_WH  1024                           // 64 x 144B
#define SM_WL  (SM_WH + 64 * 144)             // 64 x 144B
#define SM_XH  (SM_WL + 64 * 144)             // 128 x 144B
#define SM_XL  (SM_XH + 128 * 144)            // 128 x 144B
#define SM_TOTAL (SM_XL + 128 * 144)          // 56320 B

// K2 (HMMA): per block of 128 nodes, D = xh@Wh + xh@Wl + xl@Wh (fp32 acc),
//            out[n] = (1+deg)*(D[n] + bW) + b2 — stored straight from fragments.
__global__ __launch_bounds__(NT) void gnn_mma_kernel(
    const float* __restrict__ x,
    const float* __restrict__ b2,
    float* __restrict__ out,
    int n)
{
    extern __shared__ char smem[];
    const int tid = threadIdx.x;
    const int wid = tid >> 5;
    const int lid = tid & 31;
    const int g   = lid >> 2;                  // 0..7
    const int t   = lid & 3;                   // 0..3
    const int base = blockIdx.x * NPB;

    // Degree read + consume-reset + scale into smem
    if (tid < NPB) {
        const int node = base + tid;
        int d = 0;
        if (node < n) { d = g_deg[node]; g_deg[node] = 0; }
        ((float*)(smem + SM_SC))[tid] = 1.0f + (float)d;
    }
    if (tid < D_OUT) {
        ((float*)(smem + SM_BW))[tid] = g_bW[tid];
        ((float*)(smem + SM_B2))[tid] = b2[tid];
    }

    // Stage W^T hi/lo: 64 rows x 64 bf16 (=16 uint2/row) -> padded rows
    #pragma unroll
    for (int it = 0; it < 4; ++it) {
        const int u = it * NT + tid;           // 0..1023
        const int c = u >> 4, q = u & 15;
        *(uint2*)(smem + SM_WH + c * 144 + q * 8) =
            *(const uint2*)((const char*)g_WT_h + c * 128 + q * 8);
        *(uint2*)(smem + SM_WL + c * 144 + q * 8) =
            *(const uint2*)((const char*)g_WT_l + c * 128 + q * 8);
    }

    // Stage x: f32 -> bf16 hi/lo, padded rows
    #pragma unroll
    for (int it = 0; it < 8; ++it) {
        const int u = it * NT + tid;           // 0..2047
        const int row = u >> 4, q4 = u & 15;
        const int gr = (base + row < n) ? (base + row) : (n > 0 ? n - 1 : 0);
        const float4 v = ((const float4*)(x + (size_t)gr * D_IN))[q4];

        __nv_bfloat16 h0 = __float2bfloat16_rn(v.x);
        __nv_bfloat16 h1 = __float2bfloat16_rn(v.y);
        __nv_bfloat16 h2 = __float2bfloat16_rn(v.z);
        __nv_bfloat16 h3 = __float2bfloat16_rn(v.w);
        __nv_bfloat16 l0 = __float2bfloat16_rn(v.x - __bfloat162float(h0));
        __nv_bfloat16 l1 = __float2bfloat16_rn(v.y - __bfloat162float(h1));
        __nv_bfloat16 l2 = __float2bfloat16_rn(v.z - __bfloat162float(h2));
        __nv_bfloat16 l3 = __float2bfloat16_rn(v.w - __bfloat162float(h3));

        uint2 hv, lv;
        __nv_bfloat162 p;
        p = __halves2bfloat162(h0, h1); hv.x = *reinterpret_cast<uint32_t*>(&p);
        p = __halves2bfloat162(h2, h3); hv.y = *reinterpret_cast<uint32_t*>(&p);
        p = __halves2bfloat162(l0, l1); lv.x = *reinterpret_cast<uint32_t*>(&p);
        p = __halves2bfloat162(l2, l3); lv.y = *reinterpret_cast<uint32_t*>(&p);

        *(uint2*)(smem + SM_XH + row * 144 + q4 * 8) = hv;
        *(uint2*)(smem + SM_XL + row * 144 + q4 * 8) = lv;
    }
    __syncthreads();

    // ---- HMMA mainloop: warp owns rows [16*wid, 16*wid+16) ----
    float acc[32];                             // 8 n-tiles x {d0,d1,d2,d3}
    #pragma unroll
    for (int i = 0; i < 32; ++i) acc[i] = 0.f;

    const int rowA  = wid * 16 + g;            // A row for a0/a2
    const uint32_t aoff = (uint32_t)(rowA * 144 + 4 * t);
    const uint32_t boff = (uint32_t)(g * 144 + 4 * t);

    #pragma unroll
    for (int ks = 0; ks < 4; ++ks) {
        const uint32_t ak = aoff + ks * 32;
        const uint32_t ah0 = *(const uint32_t*)(smem + SM_XH + ak);
        const uint32_t ah1 = *(const uint32_t*)(smem + SM_XH + ak + 8 * 144);
        const uint32_t ah2 = *(const uint32_t*)(smem + SM_XH + ak + 16);
        const uint32_t ah3 = *(const uint32_t*)(smem + SM_XH + ak + 8 * 144 + 16);
        const uint32_t al0 = *(const uint32_t*)(smem + SM_XL + ak);
        const uint32_t al1 = *(const uint32_t*)(smem + SM_XL + ak + 8 * 144);
        const uint32_t al2 = *(const uint32_t*)(smem + SM_XL + ak + 16);
        const uint32_t al3 = *(const uint32_t*)(smem + SM_XL + ak + 8 * 144 + 16);

        #pragma unroll
        for (int nt = 0; nt < 8; ++nt) {
            const uint32_t bk = boff + nt * 8 * 144 + ks * 32;
            const uint32_t bh0 = *(const uint32_t*)(smem + SM_WH + bk);
            const uint32_t bh1 = *(const uint32_t*)(smem + SM_WH + bk + 16);
            const uint32_t bl0 = *(const uint32_t*)(smem + SM_WL + bk);
            const uint32_t bl1 = *(const uint32_t*)(smem + SM_WL + bk + 16);
            float* a = acc + nt * 4;
            mma_bf16(a[0], a[1], a[2], a[3], ah0, ah1, ah2, ah3, bh0, bh1);
            mma_bf16(a[0], a[1], a[2], a[3], ah0, ah1, ah2, ah3, bl0, bl1);
            mma_bf16(a[0], a[1], a[2], a[3], al0, al1, al2, al3, bh0, bh1);
        }
    }

    // ---- Direct-from-fragment epilogue ----
    // Thread owns D rows {r0, r0+8}, cols {8nt+2t, 8nt+2t+1}.
    {
        const float* sc = (const float*)(smem + SM_SC);
        const float* bw = (const float*)(smem + SM_BW);
        const float* bb = (const float*)(smem + SM_B2);
        const int r0 = wid * 16 + g;
        const int node0 = base + r0;
        const int node1 = node0 + 8;
        const bool v0 = (node0 < n);
        const bool v1 = (node1 < n);
        const float s0 = sc[r0];
        const float s1 = sc[r0 + 8];
        float* op0 = out + (size_t)node0 * D_OUT;
        float* op1 = out + (size_t)node1 * D_OUT;

        #pragma unroll
        for (int nt = 0; nt < 8; ++nt) {
            const int c = nt * 8 + 2 * t;
            const float2 bwv = *(const float2*)(bw + c);
            const float2 bbv = *(const float2*)(bb + c);
            const float* a = acc + nt * 4;
            if (v0) {
                float2 r;
                r.x = fmaf(s0, a[0] + bwv.x, bbv.x);
                r.y = fmaf(s0, a[1] + bwv.y, bbv.y);
                *(float2*)(op0 + c) = r;
            }
            if (v1) {
                float2 r;
                r.x = fmaf(s1, a[2] + bwv.x, bbv.x);
                r.y = fmaf(s1, a[3] + bwv.y, bbv.y);
                *(float2*)(op1 + c) = r;
            }
        }
    }
}

// ---------------------------------------------------------------------------
extern "C" void kernel_launch(void* const* d_in, const int* in_sizes, int n_in,
                              void* d_out, int out_size) {
    const float* x  = (const float*)d_in[0];
    const void*  ei = d_in[1];
    const float* W1 = (const float*)d_in[2];
    const float* b1 = (const float*)d_in[3];
    const float* W2 = (const float*)d_in[4];
    const float* b2 = (const float*)d_in[5];
    float* out = (float*)d_out;

    const int n = in_sizes[0] / D_IN;   // 100000
    const int E = in_sizes[1] / 2;      // 1000000

    const int hist_blocks = (E + 256 * EPT - 1) / (256 * EPT);
    prep_hist_kernel<<<PREP_BLOCKS + hist_blocks, 256>>>(
        (const int*)ei, W1, b1, W2, E);

    cudaFuncSetAttribute(gnn_mma_kernel,
                         cudaFuncAttributeMaxDynamicSharedMemorySize, SM_TOTAL);
    gnn_mma_kernel<<<(n + NPB - 1) / NPB, NT, SM_TOTAL>>>(x, b2, out, n);
}